// round 12
// baseline (speedup 1.0000x reference)
#include <cuda_runtime.h>
#include <cuda_fp16.h>

#define NN 50000
#define EE 800000
#define NSLOPE 0.01f
#define NB_SCAN ((NN + 1023) / 1024)      // 49
#define NGROUPS (NN / 8)                  // 6250
#define ZP 10                             // padded row stride for transposed z
#define HIST_BLOCKS 3125                  // EE / 256
#define PREP_BLOCKS 592
#define CONV_BLOCKS 888                   // 6 blocks/SM x 148 SMs

typedef unsigned long long u64;

// ---------------- scratch (zero-initialized at module load) -------------------
__device__ __half g_hA[NN * 64];
__device__ __half g_hB[NN * 64];
__device__ float2 g_edge[EE];
__device__ int    g_hist[NN];             // re-zeroed by scan_kernel
__device__ int    g_cnt[NN];              // re-zeroed by scan_kernel
__device__ int    g_row[NN + 1];
__device__ int    g_state[64];            // re-zeroed by scatter_kernel
__device__ int    g_work[8];              // re-zeroed by scan_kernel

__device__ __forceinline__ float lrelu(float v) { return v >= 0.f ? v : NSLOPE * v; }

__device__ __forceinline__ u64 pk(float a, float b) {
    u64 r; asm("mov.b64 %0,{%1,%2};" : "=l"(r) : "f"(a), "f"(b)); return r;
}
__device__ __forceinline__ void upk(u64 v, float& a, float& b) {
    asm("mov.b64 {%0,%1},%2;" : "=f"(a), "=f"(b) : "l"(v));
}
__device__ __forceinline__ u64 ffma2(u64 a, u64 b, u64 c) {
    u64 d; asm("fma.rn.f32x2 %0,%1,%2,%3;" : "=l"(d) : "l"(a), "l"(b), "l"(c)); return d;
}
__device__ __forceinline__ void h4f(uint2 v, float& a, float& b, float& c, float& d) {
    __half2 p0 = *(__half2*)&v.x, p1 = *(__half2*)&v.y;
    float2 f0 = __half22float2(p0), f1 = __half22float2(p1);
    a = f0.x; b = f0.y; c = f1.x; d = f1.y;
}

// ---------------- fused hist + prep MLP ---------------------------------------
__global__ void histprep_kernel(const int* __restrict__ ei,
                                const float* __restrict__ x,
                                const float* __restrict__ Wpin, const float* __restrict__ bpin,
                                const float* __restrict__ Wph,  const float* __restrict__ bph) {
    __shared__ float sWin[16 * 64];
    __shared__ float sWh[64 * 64];
    __shared__ float sb0[64], sb1[64];
    __shared__ float xs[8][16 * ZP];
    __shared__ float zs[8][64 * ZP];

    if (blockIdx.x < HIST_BLOCKS) {
        int e = blockIdx.x * 256 + threadIdx.x;
        if (e < EE) atomicAdd(&g_hist[ei[EE + e]], 1);
        return;
    }

    int bid = blockIdx.x - HIST_BLOCKS;
    int tid = threadIdx.x;
    for (int i = tid; i < 16 * 64; i += 256) sWin[i] = Wpin[i];
    for (int i = tid; i < 64 * 64; i += 256) sWh[i]  = Wph[i];
    if (tid < 64) { sb0[tid] = bpin[tid]; sb1[tid] = bph[tid]; }
    __syncthreads();

    int warp = tid >> 5, lane = tid & 31;
    const float2* sWinV = (const float2*)sWin;
    const float2* sWhV  = (const float2*)sWh;
    __half2* houtH = (__half2*)g_hA;
    const float2 b0 = ((const float2*)sb0)[lane];
    const float2 b1 = ((const float2*)sb1)[lane];

    for (int grp = bid * 8 + warp; grp < NGROUPS; grp += PREP_BLOCKS * 8) {
        int nbase = grp * 8;
        float4 v = *(const float4*)&x[nbase * 16 + 4 * lane];
        int nd = lane >> 2, fb = (lane & 3) * 4;
        xs[warp][(fb + 0) * ZP + nd] = v.x;
        xs[warp][(fb + 1) * ZP + nd] = v.y;
        xs[warp][(fb + 2) * ZP + nd] = v.z;
        xs[warp][(fb + 3) * ZP + nd] = v.w;
        __syncwarp();
        u64 a0[4], a1[4];
        #pragma unroll
        for (int p = 0; p < 4; p++) { a0[p] = pk(b0.x, b0.x); a1[p] = pk(b0.y, b0.y); }
        #pragma unroll
        for (int k = 0; k < 16; k++) {
            float2 wv = sWinV[k * 32 + lane];
            u64 wxx = pk(wv.x, wv.x), wyy = pk(wv.y, wv.y);
            #pragma unroll
            for (int p = 0; p < 4; p++) {
                u64 zp = *(const u64*)&xs[warp][k * ZP + 2 * p];
                a0[p] = ffma2(zp, wxx, a0[p]);
                a1[p] = ffma2(zp, wyy, a1[p]);
            }
        }
        __syncwarp();
        #pragma unroll
        for (int p = 0; p < 4; p++) {
            float x0, x1, y0, y1;
            upk(a0[p], x0, x1); upk(a1[p], y0, y1);
            *(u64*)&zs[warp][(2 * lane) * ZP + 2 * p]     = pk(lrelu(x0), lrelu(x1));
            *(u64*)&zs[warp][(2 * lane + 1) * ZP + 2 * p] = pk(lrelu(y0), lrelu(y1));
        }
        __syncwarp();
        u64 c0[4], c1[4];
        #pragma unroll
        for (int p = 0; p < 4; p++) { c0[p] = pk(b1.x, b1.x); c1[p] = pk(b1.y, b1.y); }
        #pragma unroll 16
        for (int k = 0; k < 64; k++) {
            float2 wv = sWhV[k * 32 + lane];
            u64 wxx = pk(wv.x, wv.x), wyy = pk(wv.y, wv.y);
            #pragma unroll
            for (int p = 0; p < 4; p++) {
                u64 zp = *(const u64*)&zs[warp][k * ZP + 2 * p];
                c0[p] = ffma2(zp, wxx, c0[p]);
                c1[p] = ffma2(zp, wyy, c1[p]);
            }
        }
        #pragma unroll
        for (int p = 0; p < 4; p++) {
            float x0, x1, y0, y1;
            upk(c0[p], x0, x1); upk(c1[p], y0, y1);
            houtH[(nbase + 2 * p) * 32 + lane]     = __floats2half2_rn(tanhf(x0), tanhf(y0));
            houtH[(nbase + 2 * p + 1) * 32 + lane] = __floats2half2_rn(tanhf(x1), tanhf(y1));
        }
        __syncwarp();
    }
}

// ---------------- scan ---------------------------------------------------------
__global__ void scan_kernel() {
    __shared__ int wsum[32];
    __shared__ int bprefix;
    int tid = threadIdx.x, lane = tid & 31, wid = tid >> 5;
    int b = blockIdx.x;
    int i = b * 1024 + tid;
    int v = (i < NN) ? g_hist[i] : 0;
    if (i < NN) { g_cnt[i] = 0; g_hist[i] = 0; }
    if (b == 0 && tid < 8) g_work[tid] = 0;
    int x = v;
    #pragma unroll
    for (int d = 1; d < 32; d <<= 1) {
        int t = __shfl_up_sync(0xffffffffu, x, d);
        if (lane >= d) x += t;
    }
    if (lane == 31) wsum[wid] = x;
    __syncthreads();
    if (wid == 0) {
        int s = wsum[lane];
        #pragma unroll
        for (int d = 1; d < 32; d <<= 1) {
            int t = __shfl_up_sync(0xffffffffu, s, d);
            if (lane >= d) s += t;
        }
        wsum[lane] = s;
    }
    __syncthreads();
    int warpBase = (wid > 0) ? wsum[wid - 1] : 0;
    int excl = warpBase + x - v;
    int total = wsum[31];

    if (tid == 0) {
        if (b == 0) {
            atomicExch(&g_state[0], (total << 2) | 2);
            bprefix = 0;
        } else {
            atomicExch(&g_state[b], (total << 2) | 1);
            int sum = 0, j = b - 1;
            while (true) {
                int s;
                do { s = atomicAdd(&g_state[j], 0); } while ((s & 3) == 0);
                sum += (s >> 2);
                if (s & 2) break;
                j--;
            }
            atomicExch(&g_state[b], ((sum + total) << 2) | 2);
            bprefix = sum;
        }
    }
    __syncthreads();
    int bp = bprefix;
    if (i <= NN) g_row[i] = bp + excl;
}

// ---------------- scatter -------------------------------------------------------
__global__ void scatter_kernel(const int* __restrict__ ei, const float* __restrict__ ew) {
    if (blockIdx.x == 0 && threadIdx.x < 64) g_state[threadIdx.x] = 0;
    int e = blockIdx.x * blockDim.x + threadIdx.x;
    if (e < EE) {
        int src = ei[e];
        int dst = ei[EE + e];
        int pos = g_row[dst] + atomicAdd(&g_cnt[dst], 1);
        g_edge[pos] = make_float2(__int_as_float(src), ew[e]);
    }
}

// ---------------- fused GINEConv: fp32 weights via L1, 6 blocks/SM --------------
__global__ void __launch_bounds__(256, 6)
conv_kernel(int dir, int wsel,
            const float* __restrict__ We_row, const float* __restrict__ be,
            const float* __restrict__ Wm0,  const float* __restrict__ bm0,
            const float* __restrict__ Wm1,  const float* __restrict__ bm1) {
    const __half* hin  = dir ? g_hB : g_hA;
    __half*       hout = dir ? g_hA : g_hB;
    const uint2* __restrict__ hinU  = (const uint2*)hin;
    __half2*     __restrict__ houtH = (__half2*)hout;
    const float2* __restrict__ Wm0v = (const float2*)Wm0;   // L1-resident (hot)
    const float2* __restrict__ Wm1v = (const float2*)Wm1;

    __shared__ float sWe[64], sbe[64], sbm0[64], sbm1[64];
    __shared__ float zs[8][64 * ZP];      // ~20.5 KB total SMEM

    int tid = threadIdx.x;
    if (tid < 64) { sWe[tid] = We_row[tid]; sbe[tid] = be[tid];
                    sbm0[tid] = bm0[tid];   sbm1[tid] = bm1[tid]; }
    __syncthreads();

    int warp = tid >> 5, lane = tid & 31;
    int u16 = lane >> 4, c = lane & 15;
    const float4 we4 = *(const float4*)&sWe[4 * c];
    const float4 be4 = *(const float4*)&sbe[4 * c];
    const float2 b0  = ((const float2*)sbm0)[lane];
    const float2 b1  = ((const float2*)sbm1)[lane];

    int grp;
    if (lane == 0) grp = atomicAdd(&g_work[wsel], 1);
    grp = __shfl_sync(0xffffffffu, grp, 0);
    while (grp < NGROUPS) {
        int nbase = grp * 8;
        // ---- aggregation for 8 nodes, z transposed; 8 edges/step ----
        #pragma unroll 1
        for (int n = 0; n < 8; n++) {
            int node = nbase + n;
            int rs = g_row[node];
            int re = g_row[node + 1];
            float4 acc = make_float4(0.f, 0.f, 0.f, 0.f);
            for (int base = rs; base < re; base += 32) {
                int m = re - base; if (m > 32) m = 32;
                float2 ed = make_float2(0.f, 0.f);
                if (base + lane < re) ed = __ldg(&g_edge[base + lane]);
                int   esrc = __float_as_int(ed.x);
                float ewt  = ed.y;
                int i = 0;
                #pragma unroll 1
                for (; i + 8 <= m; i += 8) {
                    int s[4]; float w[4];
                    #pragma unroll
                    for (int j = 0; j < 4; j++) {
                        s[j] = __shfl_sync(0xffffffffu, esrc, i + 2 * j + u16);
                        w[j] = __shfl_sync(0xffffffffu, ewt,  i + 2 * j + u16);
                    }
                    uint2 hv[4];
                    #pragma unroll
                    for (int j = 0; j < 4; j++) hv[j] = __ldg(&hinU[s[j] * 16 + c]);
                    #pragma unroll
                    for (int j = 0; j < 4; j++) {
                        float hx, hy, hz, hw;
                        h4f(hv[j], hx, hy, hz, hw);
                        acc.x += fmaxf(hx + fmaf(w[j], we4.x, be4.x), 0.f);
                        acc.y += fmaxf(hy + fmaf(w[j], we4.y, be4.y), 0.f);
                        acc.z += fmaxf(hz + fmaf(w[j], we4.z, be4.z), 0.f);
                        acc.w += fmaxf(hw + fmaf(w[j], we4.w, be4.w), 0.f);
                    }
                }
                for (; i < m; i += 2) {
                    int idx = i + u16;
                    int   s = __shfl_sync(0xffffffffu, esrc, idx & 31);
                    float w = __shfl_sync(0xffffffffu, ewt,  idx & 31);
                    if (idx < m) {
                        uint2 hv = __ldg(&hinU[s * 16 + c]);
                        float hx, hy, hz, hw;
                        h4f(hv, hx, hy, hz, hw);
                        acc.x += fmaxf(hx + fmaf(w, we4.x, be4.x), 0.f);
                        acc.y += fmaxf(hy + fmaf(w, we4.y, be4.y), 0.f);
                        acc.z += fmaxf(hz + fmaf(w, we4.z, be4.z), 0.f);
                        acc.w += fmaxf(hw + fmaf(w, we4.w, be4.w), 0.f);
                    }
                }
            }
            acc.x += __shfl_xor_sync(0xffffffffu, acc.x, 16);
            acc.y += __shfl_xor_sync(0xffffffffu, acc.y, 16);
            acc.z += __shfl_xor_sync(0xffffffffu, acc.z, 16);
            acc.w += __shfl_xor_sync(0xffffffffu, acc.w, 16);
            if (u16 == 0) {
                uint2 hs = __ldg(&hinU[node * 16 + c]);
                float hx, hy, hz, hw;
                h4f(hs, hx, hy, hz, hw);
                zs[warp][(4 * c + 0) * ZP + n] = acc.x + hx;
                zs[warp][(4 * c + 1) * ZP + n] = acc.y + hy;
                zs[warp][(4 * c + 2) * ZP + n] = acc.z + hz;
                zs[warp][(4 * c + 3) * ZP + n] = acc.w + hw;
            }
        }
        __syncwarp();

        // ---- MLP layer 0 (64->64) + LeakyReLU (fp32 weights via L1) ----
        u64 a0[4], a1[4];
        #pragma unroll
        for (int p = 0; p < 4; p++) { a0[p] = pk(b0.x, b0.x); a1[p] = pk(b0.y, b0.y); }
        #pragma unroll 16
        for (int k = 0; k < 64; k++) {
            float2 wv = __ldg(&Wm0v[k * 32 + lane]);
            u64 wxx = pk(wv.x, wv.x), wyy = pk(wv.y, wv.y);
            #pragma unroll
            for (int p = 0; p < 4; p++) {
                u64 zp = *(const u64*)&zs[warp][k * ZP + 2 * p];
                a0[p] = ffma2(zp, wxx, a0[p]);
                a1[p] = ffma2(zp, wyy, a1[p]);
            }
        }
        __syncwarp();
        #pragma unroll
        for (int p = 0; p < 4; p++) {
            float x0, x1, y0, y1;
            upk(a0[p], x0, x1); upk(a1[p], y0, y1);
            *(u64*)&zs[warp][(2 * lane) * ZP + 2 * p]     = pk(lrelu(x0), lrelu(x1));
            *(u64*)&zs[warp][(2 * lane + 1) * ZP + 2 * p] = pk(lrelu(y0), lrelu(y1));
        }
        __syncwarp();

        // ---- MLP layer 1 (64->64) + tanh (fp32 weights via L1) ----
        u64 c0[4], c1[4];
        #pragma unroll
        for (int p = 0; p < 4; p++) { c0[p] = pk(b1.x, b1.x); c1[p] = pk(b1.y, b1.y); }
        #pragma unroll 16
        for (int k = 0; k < 64; k++) {
            float2 wv = __ldg(&Wm1v[k * 32 + lane]);
            u64 wxx = pk(wv.x, wv.x), wyy = pk(wv.y, wv.y);
            #pragma unroll
            for (int p = 0; p < 4; p++) {
                u64 zp = *(const u64*)&zs[warp][k * ZP + 2 * p];
                c0[p] = ffma2(zp, wxx, c0[p]);
                c1[p] = ffma2(zp, wyy, c1[p]);
            }
        }
        #pragma unroll
        for (int p = 0; p < 4; p++) {
            float x0, x1, y0, y1;
            upk(c0[p], x0, x1); upk(c1[p], y0, y1);
            houtH[(nbase + 2 * p) * 32 + lane]     = __floats2half2_rn(tanhf(x0), tanhf(y0));
            houtH[(nbase + 2 * p + 1) * 32 + lane] = __floats2half2_rn(tanhf(x1), tanhf(y1));
        }
        __syncwarp();
        if (lane == 0) grp = atomicAdd(&g_work[wsel], 1);
        grp = __shfl_sync(0xffffffffu, grp, 0);
    }
}

// ---------------- post MLP: h[N,64] -> out[N,32] --------------------------------
__global__ void post_kernel(const float* __restrict__ Wq0, const float* __restrict__ bq0,
                            const float* __restrict__ Wq1, const float* __restrict__ bq1,
                            float* __restrict__ out) {
    __shared__ float sW0[64 * 64];
    __shared__ float sW1[64 * 32];
    __shared__ float sb0[64], sb1[32];
    __shared__ float zs[8][64 * ZP];

    const __half2* __restrict__ hinH = (const __half2*)g_hB;   // after conv2

    int tid = threadIdx.x;
    for (int i = tid; i < 64 * 64; i += 256) sW0[i] = Wq0[i];
    for (int i = tid; i < 64 * 32; i += 256) sW1[i] = Wq1[i];
    if (tid < 64) sb0[tid] = bq0[tid];
    if (tid < 32) sb1[tid] = bq1[tid];
    __syncthreads();

    int warp = tid >> 5, lane = tid & 31;
    const float2* sW0v = (const float2*)sW0;
    const float2 b0 = ((const float2*)sb0)[lane];
    const float  bL = sb1[lane];

    int grp;
    if (lane == 0) grp = atomicAdd(&g_work[4], 1);
    grp = __shfl_sync(0xffffffffu, grp, 0);
    while (grp < NGROUPS) {
        int nbase = grp * 8;
        #pragma unroll
        for (int n = 0; n < 8; n++) {
            float2 v = __half22float2(hinH[(nbase + n) * 32 + lane]);
            zs[warp][(2 * lane) * ZP + n]     = v.x;
            zs[warp][(2 * lane + 1) * ZP + n] = v.y;
        }
        __syncwarp();
        u64 a0[4], a1[4];
        #pragma unroll
        for (int p = 0; p < 4; p++) { a0[p] = pk(b0.x, b0.x); a1[p] = pk(b0.y, b0.y); }
        #pragma unroll 16
        for (int k = 0; k < 64; k++) {
            float2 wv = sW0v[k * 32 + lane];
            u64 wxx = pk(wv.x, wv.x), wyy = pk(wv.y, wv.y);
            #pragma unroll
            for (int p = 0; p < 4; p++) {
                u64 zp = *(const u64*)&zs[warp][k * ZP + 2 * p];
                a0[p] = ffma2(zp, wxx, a0[p]);
                a1[p] = ffma2(zp, wyy, a1[p]);
            }
        }
        __syncwarp();
        #pragma unroll
        for (int p = 0; p < 4; p++) {
            float x0, x1, y0, y1;
            upk(a0[p], x0, x1); upk(a1[p], y0, y1);
            *(u64*)&zs[warp][(2 * lane) * ZP + 2 * p]     = pk(lrelu(x0), lrelu(x1));
            *(u64*)&zs[warp][(2 * lane + 1) * ZP + 2 * p] = pk(lrelu(y0), lrelu(y1));
        }
        __syncwarp();
        u64 c0[4];
        #pragma unroll
        for (int p = 0; p < 4; p++) c0[p] = pk(bL, bL);
        #pragma unroll 16
        for (int k = 0; k < 64; k++) {
            float w = sW1[k * 32 + lane];
            u64 www = pk(w, w);
            #pragma unroll
            for (int p = 0; p < 4; p++) {
                u64 zp = *(const u64*)&zs[warp][k * ZP + 2 * p];
                c0[p] = ffma2(zp, www, c0[p]);
            }
        }
        #pragma unroll
        for (int p = 0; p < 4; p++) {
            float x0, x1;
            upk(c0[p], x0, x1);
            out[(nbase + 2 * p) * 32 + lane]     = tanhf(x0);
            out[(nbase + 2 * p + 1) * 32 + lane] = tanhf(x1);
        }
        __syncwarp();
        if (lane == 0) grp = atomicAdd(&g_work[4], 1);
        grp = __shfl_sync(0xffffffffu, grp, 0);
    }
}

// ---------------- launch ---------------------------------------------------------
extern "C" void kernel_launch(void* const* d_in, const int* in_sizes, int n_in,
                              void* d_out, int out_size) {
    const float* x     = (const float*)d_in[0];
    const int*   ei    = (const int*)  d_in[1];
    const float* ew    = (const float*)d_in[2];
    const float* Wp_in = (const float*)d_in[3];
    const float* bp_in = (const float*)d_in[4];
    const float* Wp_h  = (const float*)d_in[5];
    const float* bp_h  = (const float*)d_in[6];
    const float* We    = (const float*)d_in[7];
    const float* be    = (const float*)d_in[8];
    const float* Wm0   = (const float*)d_in[9];
    const float* bm0   = (const float*)d_in[10];
    const float* Wm1   = (const float*)d_in[11];
    const float* bm1   = (const float*)d_in[12];
    const float* Wq0   = (const float*)d_in[13];
    const float* bq0   = (const float*)d_in[14];
    const float* Wq1   = (const float*)d_in[15];
    const float* bq1   = (const float*)d_in[16];
    float* out = (float*)d_out;

    histprep_kernel<<<HIST_BLOCKS + PREP_BLOCKS, 256>>>(ei, x, Wp_in, bp_in, Wp_h, bp_h);
    scan_kernel<<<NB_SCAN, 1024>>>();
    scatter_kernel<<<(EE + 255) / 256, 256>>>(ei, ew);

    conv_kernel<<<CONV_BLOCKS, 256>>>(0, 1, We + 0 * 64, be + 0 * 64,
                                      Wm0 + 0 * 4096, bm0 + 0 * 64,
                                      Wm1 + 0 * 4096, bm1 + 0 * 64);   // A -> B
    conv_kernel<<<CONV_BLOCKS, 256>>>(1, 2, We + 1 * 64, be + 1 * 64,
                                      Wm0 + 1 * 4096, bm0 + 1 * 64,
                                      Wm1 + 1 * 4096, bm1 + 1 * 64);   // B -> A
    conv_kernel<<<CONV_BLOCKS, 256>>>(0, 3, We + 2 * 64, be + 2 * 64,
                                      Wm0 + 2 * 4096, bm0 + 2 * 64,
                                      Wm1 + 2 * 4096, bm1 + 2 * 64);   // A -> B

    post_kernel<<<592, 256>>>(Wq0, bq0, Wq1, bq1, out);
}

// round 13
// speedup vs baseline: 1.1103x; 1.1103x over previous
#include <cuda_runtime.h>
#include <cuda_fp16.h>

#define NN 50000
#define EE 800000
#define NSLOPE 0.01f
#define NB_SCAN ((NN + 1023) / 1024)      // 49
#define NGROUPS8 (NN / 8)                 // 6250 (prep)
#define NGROUPS4 (NN / 4)                 // 12500 (conv)
#define ZP 10                             // padded stride (prep/post zs)
#define ZP2 6                             // padded stride (conv zs, 4 nodes)
#define HIST_BLOCKS 3125                  // EE / 256
#define PREP_BLOCKS 592
#define CONV_BLOCKS 740                   // 5 blocks/SM x 148 SMs

typedef unsigned long long u64;

// ---------------- scratch (zero-initialized at module load) -------------------
__device__ __half g_hA[NN * 64];
__device__ __half g_hB[NN * 64];
__device__ float2 g_edge[EE];
__device__ int    g_rank[EE];             // within-dst rank from hist atomics
__device__ int    g_hist[NN];             // re-zeroed by scan_kernel
__device__ int    g_row[NN + 1];
__device__ int    g_state[64];            // re-zeroed by scatter_kernel
__device__ int    g_work[8];              // re-zeroed by scan_kernel

__device__ __forceinline__ float lrelu(float v) { return v >= 0.f ? v : NSLOPE * v; }

__device__ __forceinline__ u64 pk(float a, float b) {
    u64 r; asm("mov.b64 %0,{%1,%2};" : "=l"(r) : "f"(a), "f"(b)); return r;
}
__device__ __forceinline__ void upk(u64 v, float& a, float& b) {
    asm("mov.b64 {%0,%1},%2;" : "=f"(a), "=f"(b) : "l"(v));
}
__device__ __forceinline__ u64 ffma2(u64 a, u64 b, u64 c) {
    u64 d; asm("fma.rn.f32x2 %0,%1,%2,%3;" : "=l"(d) : "l"(a), "l"(b), "l"(c)); return d;
}
__device__ __forceinline__ void h4f(uint2 v, float& a, float& b, float& c, float& d) {
    __half2 p0 = *(__half2*)&v.x, p1 = *(__half2*)&v.y;
    float2 f0 = __half22float2(p0), f1 = __half22float2(p1);
    a = f0.x; b = f0.y; c = f1.x; d = f1.y;
}

// ---------------- fused hist(+rank) + prep MLP ---------------------------------
__global__ void histprep_kernel(const int* __restrict__ ei,
                                const float* __restrict__ x,
                                const float* __restrict__ Wpin, const float* __restrict__ bpin,
                                const float* __restrict__ Wph,  const float* __restrict__ bph) {
    __shared__ float sWin[16 * 64];
    __shared__ float sWh[64 * 64];
    __shared__ float sb0[64], sb1[64];
    __shared__ float xs[8][16 * ZP];
    __shared__ float zs[8][64 * ZP];

    if (blockIdx.x < HIST_BLOCKS) {
        int e = blockIdx.x * 256 + threadIdx.x;
        if (e < EE) {
            int old = atomicAdd(&g_hist[ei[EE + e]], 1);
            g_rank[e] = old;
        }
        return;
    }

    int bid = blockIdx.x - HIST_BLOCKS;
    int tid = threadIdx.x;
    for (int i = tid; i < 16 * 64; i += 256) sWin[i] = Wpin[i];
    for (int i = tid; i < 64 * 64; i += 256) sWh[i]  = Wph[i];
    if (tid < 64) { sb0[tid] = bpin[tid]; sb1[tid] = bph[tid]; }
    __syncthreads();

    int warp = tid >> 5, lane = tid & 31;
    const float2* sWinV = (const float2*)sWin;
    const float2* sWhV  = (const float2*)sWh;
    __half2* houtH = (__half2*)g_hA;
    const float2 b0 = ((const float2*)sb0)[lane];
    const float2 b1 = ((const float2*)sb1)[lane];

    for (int grp = bid * 8 + warp; grp < NGROUPS8; grp += PREP_BLOCKS * 8) {
        int nbase = grp * 8;
        float4 v = *(const float4*)&x[nbase * 16 + 4 * lane];
        int nd = lane >> 2, fb = (lane & 3) * 4;
        xs[warp][(fb + 0) * ZP + nd] = v.x;
        xs[warp][(fb + 1) * ZP + nd] = v.y;
        xs[warp][(fb + 2) * ZP + nd] = v.z;
        xs[warp][(fb + 3) * ZP + nd] = v.w;
        __syncwarp();
        u64 a0[4], a1[4];
        #pragma unroll
        for (int p = 0; p < 4; p++) { a0[p] = pk(b0.x, b0.x); a1[p] = pk(b0.y, b0.y); }
        #pragma unroll
        for (int k = 0; k < 16; k++) {
            float2 wv = sWinV[k * 32 + lane];
            u64 wxx = pk(wv.x, wv.x), wyy = pk(wv.y, wv.y);
            #pragma unroll
            for (int p = 0; p < 4; p++) {
                u64 zp = *(const u64*)&xs[warp][k * ZP + 2 * p];
                a0[p] = ffma2(zp, wxx, a0[p]);
                a1[p] = ffma2(zp, wyy, a1[p]);
            }
        }
        __syncwarp();
        #pragma unroll
        for (int p = 0; p < 4; p++) {
            float x0, x1, y0, y1;
            upk(a0[p], x0, x1); upk(a1[p], y0, y1);
            *(u64*)&zs[warp][(2 * lane) * ZP + 2 * p]     = pk(lrelu(x0), lrelu(x1));
            *(u64*)&zs[warp][(2 * lane + 1) * ZP + 2 * p] = pk(lrelu(y0), lrelu(y1));
        }
        __syncwarp();
        u64 c0[4], c1[4];
        #pragma unroll
        for (int p = 0; p < 4; p++) { c0[p] = pk(b1.x, b1.x); c1[p] = pk(b1.y, b1.y); }
        #pragma unroll 16
        for (int k = 0; k < 64; k++) {
            float2 wv = sWhV[k * 32 + lane];
            u64 wxx = pk(wv.x, wv.x), wyy = pk(wv.y, wv.y);
            #pragma unroll
            for (int p = 0; p < 4; p++) {
                u64 zp = *(const u64*)&zs[warp][k * ZP + 2 * p];
                c0[p] = ffma2(zp, wxx, c0[p]);
                c1[p] = ffma2(zp, wyy, c1[p]);
            }
        }
        #pragma unroll
        for (int p = 0; p < 4; p++) {
            float x0, x1, y0, y1;
            upk(c0[p], x0, x1); upk(c1[p], y0, y1);
            houtH[(nbase + 2 * p) * 32 + lane]     = __floats2half2_rn(tanhf(x0), tanhf(y0));
            houtH[(nbase + 2 * p + 1) * 32 + lane] = __floats2half2_rn(tanhf(x1), tanhf(y1));
        }
        __syncwarp();
    }
}

// ---------------- scan ---------------------------------------------------------
__global__ void scan_kernel() {
    __shared__ int wsum[32];
    __shared__ int bprefix;
    int tid = threadIdx.x, lane = tid & 31, wid = tid >> 5;
    int b = blockIdx.x;
    int i = b * 1024 + tid;
    int v = (i < NN) ? g_hist[i] : 0;
    if (i < NN) g_hist[i] = 0;            // clean for next call
    if (b == 0 && tid < 8) g_work[tid] = 0;
    int x = v;
    #pragma unroll
    for (int d = 1; d < 32; d <<= 1) {
        int t = __shfl_up_sync(0xffffffffu, x, d);
        if (lane >= d) x += t;
    }
    if (lane == 31) wsum[wid] = x;
    __syncthreads();
    if (wid == 0) {
        int s = wsum[lane];
        #pragma unroll
        for (int d = 1; d < 32; d <<= 1) {
            int t = __shfl_up_sync(0xffffffffu, s, d);
            if (lane >= d) s += t;
        }
        wsum[lane] = s;
    }
    __syncthreads();
    int warpBase = (wid > 0) ? wsum[wid - 1] : 0;
    int excl = warpBase + x - v;
    int total = wsum[31];

    if (tid == 0) {
        if (b == 0) {
            atomicExch(&g_state[0], (total << 2) | 2);
            bprefix = 0;
        } else {
            atomicExch(&g_state[b], (total << 2) | 1);
            int sum = 0, j = b - 1;
            while (true) {
                int s;
                do { s = atomicAdd(&g_state[j], 0); } while ((s & 3) == 0);
                sum += (s >> 2);
                if (s & 2) break;
                j--;
            }
            atomicExch(&g_state[b], ((sum + total) << 2) | 2);
            bprefix = sum;
        }
    }
    __syncthreads();
    int bp = bprefix;
    if (i <= NN) g_row[i] = bp + excl;
}

// ---------------- scatter (atomic-free; rank precomputed) -----------------------
__global__ void scatter_kernel(const int* __restrict__ ei, const float* __restrict__ ew) {
    if (blockIdx.x == 0 && threadIdx.x < 64) g_state[threadIdx.x] = 0;
    int e = blockIdx.x * blockDim.x + threadIdx.x;
    if (e < EE) {
        int src = ei[e];
        int dst = ei[EE + e];
        int pos = g_row[dst] + g_rank[e];
        g_edge[pos] = make_float2(__int_as_float(src), ew[e]);
    }
}

// ---------------- fused GINEConv: fp32 SMEM weights, 4-node groups, 5/SM --------
__global__ void __launch_bounds__(256, 5)
conv_kernel(int dir, int wsel,
            const float* __restrict__ We_row, const float* __restrict__ be,
            const float* __restrict__ Wm0,  const float* __restrict__ bm0,
            const float* __restrict__ Wm1,  const float* __restrict__ bm1) {
    const __half* hin  = dir ? g_hB : g_hA;
    __half*       hout = dir ? g_hA : g_hB;
    const uint2* __restrict__ hinU  = (const uint2*)hin;
    __half2*     __restrict__ houtH = (__half2*)hout;

    __shared__ float sWm0[64 * 64];       // 16 KB fp32
    __shared__ float sWm1[64 * 64];       // 16 KB fp32
    __shared__ float sWe[64], sbe[64], sbm0[64], sbm1[64];
    __shared__ float zs[8][64 * ZP2];     // 12.3 KB (4 nodes/warp-group)

    int tid = threadIdx.x;
    for (int i = tid; i < 64 * 64; i += 256) { sWm0[i] = Wm0[i]; sWm1[i] = Wm1[i]; }
    if (tid < 64) { sWe[tid] = We_row[tid]; sbe[tid] = be[tid];
                    sbm0[tid] = bm0[tid];   sbm1[tid] = bm1[tid]; }
    __syncthreads();

    int warp = tid >> 5, lane = tid & 31;
    int u16 = lane >> 4, c = lane & 15;
    const float2* sWm0v = (const float2*)sWm0;
    const float2* sWm1v = (const float2*)sWm1;
    const float4 we4 = *(const float4*)&sWe[4 * c];
    const float4 be4 = *(const float4*)&sbe[4 * c];
    const float2 b0  = ((const float2*)sbm0)[lane];
    const float2 b1  = ((const float2*)sbm1)[lane];

    int grp;
    if (lane == 0) grp = atomicAdd(&g_work[wsel], 1);
    grp = __shfl_sync(0xffffffffu, grp, 0);
    while (grp < NGROUPS4) {
        int nbase = grp * 4;
        // ---- aggregation for 4 nodes, z transposed ----
        #pragma unroll 1
        for (int n = 0; n < 4; n++) {
            int node = nbase + n;
            int rs = g_row[node];
            int re = g_row[node + 1];
            float4 acc = make_float4(0.f, 0.f, 0.f, 0.f);
            for (int base = rs; base < re; base += 32) {
                int m = re - base; if (m > 32) m = 32;
                float2 ed = make_float2(0.f, 0.f);
                if (base + lane < re) ed = __ldg(&g_edge[base + lane]);
                int   esrc = __float_as_int(ed.x);
                float ewt  = ed.y;
                int i = 0;
                #pragma unroll 1
                for (; i + 8 <= m; i += 8) {
                    int s[4]; float w[4];
                    #pragma unroll
                    for (int j = 0; j < 4; j++) {
                        s[j] = __shfl_sync(0xffffffffu, esrc, i + 2 * j + u16);
                        w[j] = __shfl_sync(0xffffffffu, ewt,  i + 2 * j + u16);
                    }
                    uint2 hv[4];
                    #pragma unroll
                    for (int j = 0; j < 4; j++) hv[j] = __ldg(&hinU[s[j] * 16 + c]);
                    #pragma unroll
                    for (int j = 0; j < 4; j++) {
                        float hx, hy, hz, hw;
                        h4f(hv[j], hx, hy, hz, hw);
                        acc.x += fmaxf(hx + fmaf(w[j], we4.x, be4.x), 0.f);
                        acc.y += fmaxf(hy + fmaf(w[j], we4.y, be4.y), 0.f);
                        acc.z += fmaxf(hz + fmaf(w[j], we4.z, be4.z), 0.f);
                        acc.w += fmaxf(hw + fmaf(w[j], we4.w, be4.w), 0.f);
                    }
                }
                for (; i < m; i += 2) {
                    int idx = i + u16;
                    int   s = __shfl_sync(0xffffffffu, esrc, idx & 31);
                    float w = __shfl_sync(0xffffffffu, ewt,  idx & 31);
                    if (idx < m) {
                        uint2 hv = __ldg(&hinU[s * 16 + c]);
                        float hx, hy, hz, hw;
                        h4f(hv, hx, hy, hz, hw);
                        acc.x += fmaxf(hx + fmaf(w, we4.x, be4.x), 0.f);
                        acc.y += fmaxf(hy + fmaf(w, we4.y, be4.y), 0.f);
                        acc.z += fmaxf(hz + fmaf(w, we4.z, be4.z), 0.f);
                        acc.w += fmaxf(hw + fmaf(w, we4.w, be4.w), 0.f);
                    }
                }
            }
            acc.x += __shfl_xor_sync(0xffffffffu, acc.x, 16);
            acc.y += __shfl_xor_sync(0xffffffffu, acc.y, 16);
            acc.z += __shfl_xor_sync(0xffffffffu, acc.z, 16);
            acc.w += __shfl_xor_sync(0xffffffffu, acc.w, 16);
            if (u16 == 0) {
                uint2 hs = __ldg(&hinU[node * 16 + c]);
                float hx, hy, hz, hw;
                h4f(hs, hx, hy, hz, hw);
                zs[warp][(4 * c + 0) * ZP2 + n] = acc.x + hx;
                zs[warp][(4 * c + 1) * ZP2 + n] = acc.y + hy;
                zs[warp][(4 * c + 2) * ZP2 + n] = acc.z + hz;
                zs[warp][(4 * c + 3) * ZP2 + n] = acc.w + hw;
            }
        }
        __syncwarp();

        // ---- MLP layer 0 (64->64) + LeakyReLU (fp32 SMEM weights) ----
        u64 a0[2], a1[2];
        #pragma unroll
        for (int p = 0; p < 2; p++) { a0[p] = pk(b0.x, b0.x); a1[p] = pk(b0.y, b0.y); }
        #pragma unroll 16
        for (int k = 0; k < 64; k++) {
            float2 wv = sWm0v[k * 32 + lane];
            u64 wxx = pk(wv.x, wv.x), wyy = pk(wv.y, wv.y);
            #pragma unroll
            for (int p = 0; p < 2; p++) {
                u64 zp = *(const u64*)&zs[warp][k * ZP2 + 2 * p];
                a0[p] = ffma2(zp, wxx, a0[p]);
                a1[p] = ffma2(zp, wyy, a1[p]);
            }
        }
        __syncwarp();
        #pragma unroll
        for (int p = 0; p < 2; p++) {
            float x0, x1, y0, y1;
            upk(a0[p], x0, x1); upk(a1[p], y0, y1);
            *(u64*)&zs[warp][(2 * lane) * ZP2 + 2 * p]     = pk(lrelu(x0), lrelu(x1));
            *(u64*)&zs[warp][(2 * lane + 1) * ZP2 + 2 * p] = pk(lrelu(y0), lrelu(y1));
        }
        __syncwarp();

        // ---- MLP layer 1 (64->64) + tanh (fp32 SMEM weights) ----
        u64 c0[2], c1[2];
        #pragma unroll
        for (int p = 0; p < 2; p++) { c0[p] = pk(b1.x, b1.x); c1[p] = pk(b1.y, b1.y); }
        #pragma unroll 16
        for (int k = 0; k < 64; k++) {
            float2 wv = sWm1v[k * 32 + lane];
            u64 wxx = pk(wv.x, wv.x), wyy = pk(wv.y, wv.y);
            #pragma unroll
            for (int p = 0; p < 2; p++) {
                u64 zp = *(const u64*)&zs[warp][k * ZP2 + 2 * p];
                c0[p] = ffma2(zp, wxx, c0[p]);
                c1[p] = ffma2(zp, wyy, c1[p]);
            }
        }
        #pragma unroll
        for (int p = 0; p < 2; p++) {
            float x0, x1, y0, y1;
            upk(c0[p], x0, x1); upk(c1[p], y0, y1);
            houtH[(nbase + 2 * p) * 32 + lane]     = __floats2half2_rn(tanhf(x0), tanhf(y0));
            houtH[(nbase + 2 * p + 1) * 32 + lane] = __floats2half2_rn(tanhf(x1), tanhf(y1));
        }
        __syncwarp();
        if (lane == 0) grp = atomicAdd(&g_work[wsel], 1);
        grp = __shfl_sync(0xffffffffu, grp, 0);
    }
}

// ---------------- post MLP: h[N,64] -> out[N,32] --------------------------------
__global__ void post_kernel(const float* __restrict__ Wq0, const float* __restrict__ bq0,
                            const float* __restrict__ Wq1, const float* __restrict__ bq1,
                            float* __restrict__ out) {
    __shared__ float sW0[64 * 64];
    __shared__ float sW1[64 * 32];
    __shared__ float sb0[64], sb1[32];
    __shared__ float zs[8][64 * ZP];

    const __half2* __restrict__ hinH = (const __half2*)g_hB;   // after conv2

    int tid = threadIdx.x;
    for (int i = tid; i < 64 * 64; i += 256) sW0[i] = Wq0[i];
    for (int i = tid; i < 64 * 32; i += 256) sW1[i] = Wq1[i];
    if (tid < 64) sb0[tid] = bq0[tid];
    if (tid < 32) sb1[tid] = bq1[tid];
    __syncthreads();

    int warp = tid >> 5, lane = tid & 31;
    const float2* sW0v = (const float2*)sW0;
    const float2 b0 = ((const float2*)sb0)[lane];
    const float  bL = sb1[lane];

    int grp;
    if (lane == 0) grp = atomicAdd(&g_work[4], 1);
    grp = __shfl_sync(0xffffffffu, grp, 0);
    while (grp < NGROUPS8) {
        int nbase = grp * 8;
        #pragma unroll
        for (int n = 0; n < 8; n++) {
            float2 v = __half22float2(hinH[(nbase + n) * 32 + lane]);
            zs[warp][(2 * lane) * ZP + n]     = v.x;
            zs[warp][(2 * lane + 1) * ZP + n] = v.y;
        }
        __syncwarp();
        u64 a0[4], a1[4];
        #pragma unroll
        for (int p = 0; p < 4; p++) { a0[p] = pk(b0.x, b0.x); a1[p] = pk(b0.y, b0.y); }
        #pragma unroll 16
        for (int k = 0; k < 64; k++) {
            float2 wv = sW0v[k * 32 + lane];
            u64 wxx = pk(wv.x, wv.x), wyy = pk(wv.y, wv.y);
            #pragma unroll
            for (int p = 0; p < 4; p++) {
                u64 zp = *(const u64*)&zs[warp][k * ZP + 2 * p];
                a0[p] = ffma2(zp, wxx, a0[p]);
                a1[p] = ffma2(zp, wyy, a1[p]);
            }
        }
        __syncwarp();
        #pragma unroll
        for (int p = 0; p < 4; p++) {
            float x0, x1, y0, y1;
            upk(a0[p], x0, x1); upk(a1[p], y0, y1);
            *(u64*)&zs[warp][(2 * lane) * ZP + 2 * p]     = pk(lrelu(x0), lrelu(x1));
            *(u64*)&zs[warp][(2 * lane + 1) * ZP + 2 * p] = pk(lrelu(y0), lrelu(y1));
        }
        __syncwarp();
        u64 c0[4];
        #pragma unroll
        for (int p = 0; p < 4; p++) c0[p] = pk(bL, bL);
        #pragma unroll 16
        for (int k = 0; k < 64; k++) {
            float w = sW1[k * 32 + lane];
            u64 www = pk(w, w);
            #pragma unroll
            for (int p = 0; p < 4; p++) {
                u64 zp = *(const u64*)&zs[warp][k * ZP + 2 * p];
                c0[p] = ffma2(zp, www, c0[p]);
            }
        }
        #pragma unroll
        for (int p = 0; p < 4; p++) {
            float x0, x1;
            upk(c0[p], x0, x1);
            out[(nbase + 2 * p) * 32 + lane]     = tanhf(x0);
            out[(nbase + 2 * p + 1) * 32 + lane] = tanhf(x1);
        }
        __syncwarp();
        if (lane == 0) grp = atomicAdd(&g_work[4], 1);
        grp = __shfl_sync(0xffffffffu, grp, 0);
    }
}

// ---------------- launch ---------------------------------------------------------
extern "C" void kernel_launch(void* const* d_in, const int* in_sizes, int n_in,
                              void* d_out, int out_size) {
    const float* x     = (const float*)d_in[0];
    const int*   ei    = (const int*)  d_in[1];
    const float* ew    = (const float*)d_in[2];
    const float* Wp_in = (const float*)d_in[3];
    const float* bp_in = (const float*)d_in[4];
    const float* Wp_h  = (const float*)d_in[5];
    const float* bp_h  = (const float*)d_in[6];
    const float* We    = (const float*)d_in[7];
    const float* be    = (const float*)d_in[8];
    const float* Wm0   = (const float*)d_in[9];
    const float* bm0   = (const float*)d_in[10];
    const float* Wm1   = (const float*)d_in[11];
    const float* bm1   = (const float*)d_in[12];
    const float* Wq0   = (const float*)d_in[13];
    const float* bq0   = (const float*)d_in[14];
    const float* Wq1   = (const float*)d_in[15];
    const float* bq1   = (const float*)d_in[16];
    float* out = (float*)d_out;

    histprep_kernel<<<HIST_BLOCKS + PREP_BLOCKS, 256>>>(ei, x, Wp_in, bp_in, Wp_h, bp_h);
    scan_kernel<<<NB_SCAN, 1024>>>();
    scatter_kernel<<<(EE + 255) / 256, 256>>>(ei, ew);

    conv_kernel<<<CONV_BLOCKS, 256>>>(0, 1, We + 0 * 64, be + 0 * 64,
                                      Wm0 + 0 * 4096, bm0 + 0 * 64,
                                      Wm1 + 0 * 4096, bm1 + 0 * 64);   // A -> B
    conv_kernel<<<CONV_BLOCKS, 256>>>(1, 2, We + 1 * 64, be + 1 * 64,
                                      Wm0 + 1 * 4096, bm0 + 1 * 64,
                                      Wm1 + 1 * 4096, bm1 + 1 * 64);   // B -> A
    conv_kernel<<<CONV_BLOCKS, 256>>>(0, 3, We + 2 * 64, be + 2 * 64,
                                      Wm0 + 2 * 4096, bm0 + 2 * 64,
                                      Wm1 + 2 * 4096, bm1 + 2 * 64);   // A -> B

    post_kernel<<<592, 256>>>(Wq0, bq0, Wq1, bq1, out);
}